// round 1
// baseline (speedup 1.0000x reference)
#include <cuda_runtime.h>

// Problem constants
#define Bq   512
#define Tt   365
#define Ff   16
#define Hh   256
#define G4   1024   // 4*H
#define NC   128    // CTAs
#define BS   4      // batch rows per CTA (NC*BS == Bq)
#define NT   256    // threads per CTA

// ---------------------------------------------------------------------------
// Device scratch: transposed weights [K][4H] and fused biases (L2-resident).
// ---------------------------------------------------------------------------
__device__ float g_wih1t[Ff * G4];
__device__ float g_whh1t[Hh * G4];
__device__ float g_wih2t[Hh * G4];
__device__ float g_whh2t[Hh * G4];
__device__ float g_bias1[G4];
__device__ float g_bias2[G4];

// ---------------------------------------------------------------------------
// Packed f32x2 helpers (Blackwell FFMA2 via PTX; 2 fp32 MACs / instruction)
// ---------------------------------------------------------------------------
typedef unsigned long long u64;

__device__ __forceinline__ u64 pack2(float lo, float hi) {
    u64 r; asm("mov.b64 %0, {%1, %2};" : "=l"(r) : "f"(lo), "f"(hi)); return r;
}
__device__ __forceinline__ float2 unpack2(u64 v) {
    float2 r; asm("mov.b64 {%0, %1}, %2;" : "=f"(r.x), "=f"(r.y) : "l"(v)); return r;
}
__device__ __forceinline__ u64 fma2(u64 a, u64 b, u64 c) {
    u64 d; asm("fma.rn.f32x2 %0, %1, %2, %3;" : "=l"(d) : "l"(a), "l"(b), "l"(c)); return d;
}

__device__ __forceinline__ float sigf(float x) {
    return 1.0f / (1.0f + __expf(-x));
}

// acc[b][0] holds gates g0+0..1, acc[b][1] holds g0+2..3 (packed f32x2)
__device__ __forceinline__ void fma_b(u64 acc[BS][2], int b, float hv, u64 wlo, u64 whi) {
    u64 a = pack2(hv, hv);
    acc[b][0] = fma2(a, wlo, acc[b][0]);
    acc[b][1] = fma2(a, whi, acc[b][1]);
}

// ---------------------------------------------------------------------------
// Prep kernel: transpose weights to [K][4H] layout, fuse biases.
// W_ih1: [1024,16], W_hh*: [1024,256] row-major (torch layout).
// ---------------------------------------------------------------------------
__global__ void prep_kernel(const float* __restrict__ wih1, const float* __restrict__ whh1,
                            const float* __restrict__ bih1, const float* __restrict__ bhh1,
                            const float* __restrict__ wih2, const float* __restrict__ whh2,
                            const float* __restrict__ bih2, const float* __restrict__ bhh2) {
    int idx = blockIdx.x * blockDim.x + threadIdx.x;
    if (idx < Ff * G4) {
        int g = idx / Ff, k = idx % Ff;
        g_wih1t[k * G4 + g] = wih1[idx];
    }
    if (idx < Hh * G4) {
        int g = idx / Hh, k = idx % Hh;
        g_whh1t[k * G4 + g] = whh1[idx];
        g_wih2t[k * G4 + g] = wih2[idx];
        g_whh2t[k * G4 + g] = whh2[idx];
    }
    if (idx < G4) {
        g_bias1[idx] = bih1[idx] + bhh1[idx];
        g_bias2[idx] = bih2[idx] + bhh2[idx];
    }
}

// ---------------------------------------------------------------------------
// Fused 2-layer LSTM recurrence. One CTA = BS batch rows, full time loop.
// ---------------------------------------------------------------------------
__global__ void __launch_bounds__(NT, 1)
lstm_kernel(const float* __restrict__ x,
            const float* __restrict__ wlin, const float* __restrict__ blin,
            float* __restrict__ out) {
    __shared__ float zs[BS][G4];     // gate pre-activations
    __shared__ float h1s[Hh][BS];    // k-major hidden state (float4 per k)
    __shared__ float c1s[Hh][BS];
    __shared__ float h2s[Hh][BS];
    __shared__ float c2s[Hh][BS];
    __shared__ float xs[Ff][BS];     // x_t staged

    const int tid = threadIdx.x;
    const int b0  = blockIdx.x * BS;
    const int g0  = tid * 4;         // this thread's 4 gate columns

    const float* __restrict__ wih1p = &g_wih1t[g0];
    const float* __restrict__ whh1p = &g_whh1t[g0];
    const float* __restrict__ wih2p = &g_wih2t[g0];
    const float* __restrict__ whh2p = &g_whh2t[g0];

    // zero initial state (tid == 0..255 == Hh-1)
    float4 z4 = make_float4(0.f, 0.f, 0.f, 0.f);
    *(float4*)&h1s[tid][0] = z4;
    *(float4*)&c1s[tid][0] = z4;
    *(float4*)&h2s[tid][0] = z4;
    *(float4*)&c2s[tid][0] = z4;
    __syncthreads();

    for (int t = 0; t < Tt; ++t) {
        // ---- stage x_t for this CTA's batch rows ----
        if (tid < Ff * BS) {
            int k = tid >> 2, b = tid & 3;
            xs[k][b] = x[((size_t)(b0 + b) * Tt + t) * Ff + k];
        }
        __syncthreads();

        // ==================== LAYER 1 gates ====================
        {
            u64 acc[BS][2];
            float4 bb = *(const float4*)&g_bias1[g0];
            u64 blo = pack2(bb.x, bb.y), bhi = pack2(bb.z, bb.w);
            #pragma unroll
            for (int b = 0; b < BS; ++b) { acc[b][0] = blo; acc[b][1] = bhi; }

            // x @ W_ih1^T  (K = 16)
            #pragma unroll
            for (int k = 0; k < Ff; ++k) {
                float4 w = *(const float4*)(wih1p + (size_t)k * G4);
                u64 wlo = pack2(w.x, w.y), whi = pack2(w.z, w.w);
                float4 hv = *(const float4*)&xs[k][0];
                fma_b(acc, 0, hv.x, wlo, whi);
                fma_b(acc, 1, hv.y, wlo, whi);
                fma_b(acc, 2, hv.z, wlo, whi);
                fma_b(acc, 3, hv.w, wlo, whi);
            }
            // h1 @ W_hh1^T  (K = 256)
            #pragma unroll 8
            for (int k = 0; k < Hh; ++k) {
                float4 w = *(const float4*)(whh1p + (size_t)k * G4);
                u64 wlo = pack2(w.x, w.y), whi = pack2(w.z, w.w);
                float4 hv = *(const float4*)&h1s[k][0];
                fma_b(acc, 0, hv.x, wlo, whi);
                fma_b(acc, 1, hv.y, wlo, whi);
                fma_b(acc, 2, hv.z, wlo, whi);
                fma_b(acc, 3, hv.w, wlo, whi);
            }
            #pragma unroll
            for (int b = 0; b < BS; ++b) {
                float2 lo = unpack2(acc[b][0]), hi = unpack2(acc[b][1]);
                *(float4*)&zs[b][g0] = make_float4(lo.x, lo.y, hi.x, hi.y);
            }
        }
        __syncthreads();

        // ==================== LAYER 1 update (u = tid) ====================
        {
            const int u = tid;
            float4 cold = *(float4*)&c1s[u][0];
            float co[4] = {cold.x, cold.y, cold.z, cold.w};
            float cn[4], hn[4];
            #pragma unroll
            for (int b = 0; b < BS; ++b) {
                float iv = zs[b][u];
                float fv = zs[b][u + Hh];
                float gv = zs[b][u + 2 * Hh];
                float ov = zs[b][u + 3 * Hh];
                float c  = sigf(fv) * co[b] + sigf(iv) * tanhf(gv);
                cn[b] = c;
                hn[b] = sigf(ov) * tanhf(c);
            }
            *(float4*)&c1s[u][0] = make_float4(cn[0], cn[1], cn[2], cn[3]);
            *(float4*)&h1s[u][0] = make_float4(hn[0], hn[1], hn[2], hn[3]);
        }
        __syncthreads();

        // ==================== LAYER 2 gates ====================
        {
            u64 acc[BS][2];
            float4 bb = *(const float4*)&g_bias2[g0];
            u64 blo = pack2(bb.x, bb.y), bhi = pack2(bb.z, bb.w);
            #pragma unroll
            for (int b = 0; b < BS; ++b) { acc[b][0] = blo; acc[b][1] = bhi; }

            // h1_new @ W_ih2^T + h2 @ W_hh2^T  (K = 256 each)
            #pragma unroll 4
            for (int k = 0; k < Hh; ++k) {
                float4 wa = *(const float4*)(wih2p + (size_t)k * G4);
                float4 wb = *(const float4*)(whh2p + (size_t)k * G4);
                u64 walo = pack2(wa.x, wa.y), wahi = pack2(wa.z, wa.w);
                u64 wblo = pack2(wb.x, wb.y), wbhi = pack2(wb.z, wb.w);
                float4 h1v = *(const float4*)&h1s[k][0];
                float4 h2v = *(const float4*)&h2s[k][0];
                fma_b(acc, 0, h1v.x, walo, wahi);  fma_b(acc, 0, h2v.x, wblo, wbhi);
                fma_b(acc, 1, h1v.y, walo, wahi);  fma_b(acc, 1, h2v.y, wblo, wbhi);
                fma_b(acc, 2, h1v.z, walo, wahi);  fma_b(acc, 2, h2v.z, wblo, wbhi);
                fma_b(acc, 3, h1v.w, walo, wahi);  fma_b(acc, 3, h2v.w, wblo, wbhi);
            }
            #pragma unroll
            for (int b = 0; b < BS; ++b) {
                float2 lo = unpack2(acc[b][0]), hi = unpack2(acc[b][1]);
                *(float4*)&zs[b][g0] = make_float4(lo.x, lo.y, hi.x, hi.y);
            }
        }
        __syncthreads();

        // ==================== LAYER 2 update ====================
        {
            const int u = tid;
            float4 cold = *(float4*)&c2s[u][0];
            float co[4] = {cold.x, cold.y, cold.z, cold.w};
            float cn[4], hn[4];
            #pragma unroll
            for (int b = 0; b < BS; ++b) {
                float iv = zs[b][u];
                float fv = zs[b][u + Hh];
                float gv = zs[b][u + 2 * Hh];
                float ov = zs[b][u + 3 * Hh];
                float c  = sigf(fv) * co[b] + sigf(iv) * tanhf(gv);
                cn[b] = c;
                hn[b] = sigf(ov) * tanhf(c);
            }
            *(float4*)&c2s[u][0] = make_float4(cn[0], cn[1], cn[2], cn[3]);
            *(float4*)&h2s[u][0] = make_float4(hn[0], hn[1], hn[2], hn[3]);
        }
        __syncthreads();
    }

    // ==================== final linear head: out[b] = h2_T . W_lin + b ====
    if (tid < 32 * BS) {
        int b = tid >> 5, lane = tid & 31;
        float s = 0.f;
        #pragma unroll
        for (int k = lane; k < Hh; k += 32) s += h2s[k][b] * wlin[k];
        #pragma unroll
        for (int off = 16; off; off >>= 1) s += __shfl_xor_sync(0xffffffffu, s, off);
        if (lane == 0) out[b0 + b] = s + blin[0];
    }
}

// ---------------------------------------------------------------------------
extern "C" void kernel_launch(void* const* d_in, const int* in_sizes, int n_in,
                              void* d_out, int out_size) {
    const float* x    = (const float*)d_in[0];
    const float* wih1 = (const float*)d_in[1];
    const float* whh1 = (const float*)d_in[2];
    const float* bih1 = (const float*)d_in[3];
    const float* bhh1 = (const float*)d_in[4];
    const float* wih2 = (const float*)d_in[5];
    const float* whh2 = (const float*)d_in[6];
    const float* bih2 = (const float*)d_in[7];
    const float* bhh2 = (const float*)d_in[8];
    const float* wlin = (const float*)d_in[9];
    const float* blin = (const float*)d_in[10];
    float* out = (float*)d_out;

    prep_kernel<<<(Hh * G4 + 255) / 256, 256>>>(wih1, whh1, bih1, bhh1,
                                                wih2, whh2, bih2, bhh2);
    lstm_kernel<<<NC, NT>>>(x, wlin, blin, out);
}